// round 1
// baseline (speedup 1.0000x reference)
#include <cuda_runtime.h>
#include <cstdint>

typedef unsigned long long ull;

// ---------------- scratch (static device globals; no allocs allowed) --------
// q,k,v: [4, 4096, 1024] f32 = 67MB each. scores: [4, 4096, 4096] f32 = 268MB.
__device__ float g_q[4LL * 4096 * 1024];
__device__ float g_k[4LL * 4096 * 1024];
__device__ float g_v[4LL * 4096 * 1024];
__device__ float g_s[4LL * 4096 * 4096];

// ---------------- packed f32x2 helpers (sm_103a FFMA2 path) -----------------
__device__ __forceinline__ ull fma2(ull a, ull b, ull c) {
    ull d;
    asm("fma.rn.f32x2 %0, %1, %2, %3;" : "=l"(d) : "l"(a), "l"(b), "l"(c));
    return d;
}

__device__ __forceinline__ ull pack_dup(float x) {
    ull d;
    unsigned u = __float_as_uint(x);
    asm("mov.b64 %0, {%1, %2};" : "=l"(d) : "r"(u), "r"(u));
    return d;
}

__device__ __forceinline__ float2 unpack2(ull v) {
    unsigned lo, hi;
    asm("mov.b64 {%0, %1}, %2;" : "=r"(lo), "=r"(hi) : "l"(v));
    float2 r;
    r.x = __uint_as_float(lo);
    r.y = __uint_as_float(hi);
    return r;
}

// ---------------- generic 128x128 tile GEMM body ----------------------------
// C[m,n] = alpha * sum_k A[m,k] * B(k,n) + bias[n]
//   TRANS_B=false: B is [K, N] row-major (ldb = N stride)
//   TRANS_B=true : B is [N, K] row-major (ldb = K stride), i.e. C = A * B^T
// Tile: 128x128, blockDim 256, 8x8 outputs/thread, K-chunk 8.
// Accumulators are row-pair packed f32x2 (FFMA2) -> 2x fp32 throughput.
template <bool TRANS_B, bool HAS_BIAS>
__device__ __forceinline__ void gemm_body(
    const float* __restrict__ A, int lda,
    const float* __restrict__ B, int ldb,
    float* __restrict__ C, int ldc,
    const float* __restrict__ bias, float alpha, int K)
{
    __shared__ __align__(16) float As[8][132];
    __shared__ __align__(16) float Bs[8][132];

    const int t  = threadIdx.x;
    const int tx = t & 15;        // 0..15 -> col group (8 cols)
    const int ty = t >> 4;        // 0..15 -> row group (8 rows)
    const int m0 = blockIdx.y * 128;
    const int n0 = blockIdx.x * 128;

    const int arow = t >> 1;          // 0..127
    const int aseg = (t & 1) * 4;     // 0 or 4
    const int brow = t >> 5;          // 0..7   (NN loader)
    const int bcol = (t & 31) * 4;    // 0..124 (NN loader)

    const float* Aptr = A + (size_t)(m0 + arow) * lda + aseg;
    const float* Bptr;
    if (TRANS_B) Bptr = B + (size_t)(n0 + arow) * ldb + aseg;
    else         Bptr = B + (size_t)brow * ldb + n0 + bcol;

    ull acc[4][8];
#pragma unroll
    for (int p = 0; p < 4; p++)
#pragma unroll
        for (int j = 0; j < 8; j++) acc[p][j] = 0ULL;

    for (int k0 = 0; k0 < K; k0 += 8) {
        float4 av = *(const float4*)(Aptr + k0);
        float4 bv;
        if (TRANS_B) bv = *(const float4*)(Bptr + k0);
        else         bv = *(const float4*)(Bptr + (size_t)k0 * ldb);

        __syncthreads();  // previous chunk's readers done before overwrite
        As[aseg + 0][arow] = av.x;
        As[aseg + 1][arow] = av.y;
        As[aseg + 2][arow] = av.z;
        As[aseg + 3][arow] = av.w;
        if (TRANS_B) {
            Bs[aseg + 0][arow] = bv.x;
            Bs[aseg + 1][arow] = bv.y;
            Bs[aseg + 2][arow] = bv.z;
            Bs[aseg + 3][arow] = bv.w;
        } else {
            *(float4*)&Bs[brow][bcol] = bv;
        }
        __syncthreads();

#pragma unroll
        for (int k = 0; k < 8; k++) {
            const ull* ap = (const ull*)&As[k][ty * 8];   // 4 row-pairs
            ull a0 = ap[0], a1 = ap[1], a2 = ap[2], a3 = ap[3];

            const float* bf = &Bs[k][tx * 8];
            float4 bA = *(const float4*)bf;
            float4 bB = *(const float4*)(bf + 4);
            ull bd[8];
            bd[0] = pack_dup(bA.x); bd[1] = pack_dup(bA.y);
            bd[2] = pack_dup(bA.z); bd[3] = pack_dup(bA.w);
            bd[4] = pack_dup(bB.x); bd[5] = pack_dup(bB.y);
            bd[6] = pack_dup(bB.z); bd[7] = pack_dup(bB.w);

#pragma unroll
            for (int j = 0; j < 8; j++) {
                acc[0][j] = fma2(a0, bd[j], acc[0][j]);
                acc[1][j] = fma2(a1, bd[j], acc[1][j]);
                acc[2][j] = fma2(a2, bd[j], acc[2][j]);
                acc[3][j] = fma2(a3, bd[j], acc[3][j]);
            }
        }
    }

    float bias8[8];
#pragma unroll
    for (int j = 0; j < 8; j++)
        bias8[j] = HAS_BIAS ? bias[n0 + tx * 8 + j] : 0.0f;

#pragma unroll
    for (int p = 0; p < 4; p++) {
        float lo[8], hi[8];
#pragma unroll
        for (int j = 0; j < 8; j++) {
            float2 c = unpack2(acc[p][j]);
            lo[j] = fmaf(alpha, c.x, bias8[j]);
            hi[j] = fmaf(alpha, c.y, bias8[j]);
        }
        size_t base = (size_t)(m0 + ty * 8 + 2 * p) * ldc + (n0 + tx * 8);
        *(float4*)(C + base)           = make_float4(lo[0], lo[1], lo[2], lo[3]);
        *(float4*)(C + base + 4)       = make_float4(lo[4], lo[5], lo[6], lo[7]);
        *(float4*)(C + base + ldc)     = make_float4(hi[0], hi[1], hi[2], hi[3]);
        *(float4*)(C + base + ldc + 4) = make_float4(hi[4], hi[5], hi[6], hi[7]);
    }
}

// ---------------- kernels ---------------------------------------------------

// QKV projection: x[16384,1024] * W[1024,1024] + b -> q/k/v. z selects which.
__global__ __launch_bounds__(256) void qkv_kernel(
    const float* __restrict__ x,
    const float* __restrict__ Wq, const float* __restrict__ bq,
    const float* __restrict__ Wk, const float* __restrict__ bk,
    const float* __restrict__ Wv, const float* __restrict__ bv)
{
    const float* W;
    const float* bb;
    float* out;
    if (blockIdx.z == 0)      { W = Wq; bb = bq; out = g_q; }
    else if (blockIdx.z == 1) { W = Wk; bb = bk; out = g_k; }
    else                      { W = Wv; bb = bv; out = g_v; }
    gemm_body<false, true>(x, 1024, W, 1024, out, 1024, bb, 1.0f, 1024);
}

// scores[b] = (q[b] * k[b]^T) / 32   (M=N=4096, K=1024)
__global__ __launch_bounds__(256) void scores_kernel()
{
    size_t b = blockIdx.z;
    gemm_body<true, false>(g_q + b * 4096 * 1024, 1024,
                           g_k + b * 4096 * 1024, 1024,
                           g_s + b * 4096 * 4096, 4096,
                           nullptr, 0.03125f, 1024);
}

// Row softmax over 16384 rows of width 4096 (in place on g_s).
__global__ __launch_bounds__(256) void softmax_kernel()
{
    size_t row = blockIdx.x;
    float4* p4 = (float4*)(g_s + row * 4096);
    int t = threadIdx.x;
    int lane = t & 31, wid = t >> 5;
    __shared__ float red[8];

    float4 v[4];
    float mx = -1e30f;
#pragma unroll
    for (int i = 0; i < 4; i++) {
        v[i] = p4[t + 256 * i];
        mx = fmaxf(mx, fmaxf(fmaxf(v[i].x, v[i].y), fmaxf(v[i].z, v[i].w)));
    }
#pragma unroll
    for (int o = 16; o; o >>= 1) mx = fmaxf(mx, __shfl_xor_sync(0xffffffffu, mx, o));
    if (lane == 0) red[wid] = mx;
    __syncthreads();
    if (t == 0) {
        float m = red[0];
#pragma unroll
        for (int i = 1; i < 8; i++) m = fmaxf(m, red[i]);
        red[0] = m;
    }
    __syncthreads();
    mx = red[0];
    __syncthreads();  // everyone has read red[0] before it is reused

    float sum = 0.0f;
#pragma unroll
    for (int i = 0; i < 4; i++) {
        v[i].x = __expf(v[i].x - mx);
        v[i].y = __expf(v[i].y - mx);
        v[i].z = __expf(v[i].z - mx);
        v[i].w = __expf(v[i].w - mx);
        sum += (v[i].x + v[i].y) + (v[i].z + v[i].w);
    }
#pragma unroll
    for (int o = 16; o; o >>= 1) sum += __shfl_xor_sync(0xffffffffu, sum, o);
    if (lane == 0) red[wid] = sum;
    __syncthreads();
    if (t == 0) {
        float s = 0.0f;
#pragma unroll
        for (int i = 0; i < 8; i++) s += red[i];
        red[0] = s;
    }
    __syncthreads();
    float inv = 1.0f / red[0];
#pragma unroll
    for (int i = 0; i < 4; i++) {
        v[i].x *= inv; v[i].y *= inv; v[i].z *= inv; v[i].w *= inv;
        p4[t + 256 * i] = v[i];
    }
}

// out[b] = weights[b] * v[b]  (M=4096, N=1024, K=4096)
__global__ __launch_bounds__(256) void av_kernel(float* __restrict__ out)
{
    size_t b = blockIdx.z;
    gemm_body<false, false>(g_s + b * 4096 * 4096, 4096,
                            g_v + b * 4096 * 1024, 1024,
                            out + b * 4096 * 1024, 1024,
                            nullptr, 1.0f, 4096);
}

// ---------------- entry -----------------------------------------------------
extern "C" void kernel_launch(void* const* d_in, const int* in_sizes, int n_in,
                              void* d_out, int out_size)
{
    (void)in_sizes; (void)n_in; (void)out_size;
    const float* x  = (const float*)d_in[0];
    const float* Wq = (const float*)d_in[1];
    const float* bq = (const float*)d_in[2];
    const float* Wk = (const float*)d_in[3];
    const float* bk = (const float*)d_in[4];
    const float* Wv = (const float*)d_in[5];
    const float* bv = (const float*)d_in[6];
    float* out = (float*)d_out;

    dim3 blk(256);
    qkv_kernel<<<dim3(8, 128, 3), blk>>>(x, Wq, bq, Wk, bk, Wv, bv);
    scores_kernel<<<dim3(32, 32, 4), blk>>>();
    softmax_kernel<<<16384, blk>>>();
    av_kernel<<<dim3(8, 32, 4), blk>>>(out);
}

// round 11
// speedup vs baseline: 1.9653x; 1.9653x over previous
#include <cuda_runtime.h>
#include <cuda_bf16.h>
#include <cstdint>

typedef uint32_t U32;
typedef uint64_t U64;
typedef __nv_bfloat16 bf16;

// ---------------- problem sizes ---------------------------------------------
#define MT 16384              // B*S rows
#define F  1024               // in_features = hidden
#define S  4096               // seq len
#define NB 4                  // batch

// ---------------- scratch (static device globals) ---------------------------
__device__ bf16 g_xh[(size_t)MT * F], g_xl[(size_t)MT * F];
__device__ bf16 g_wth[3 * (size_t)F * F], g_wtl[3 * (size_t)F * F];
__device__ bf16 g_qh[(size_t)MT * F], g_ql[(size_t)MT * F];
__device__ bf16 g_kh[(size_t)MT * F], g_kl[(size_t)MT * F];
__device__ bf16 g_vth[(size_t)NB * F * S], g_vtl[(size_t)NB * F * S];
__device__ float g_s[(size_t)NB * S * S];
__device__ bf16 g_ph[(size_t)NB * S * S], g_pl[(size_t)NB * S * S];

// ---------------- helpers ----------------------------------------------------
__device__ __forceinline__ U32 smem_u32(const void* p) {
    U32 a;
    asm("{ .reg .u64 t; cvta.to.shared.u64 t, %1; cvt.u32.u64 %0, t; }" : "=r"(a) : "l"(p));
    return a;
}

__device__ __forceinline__ U32 pack2(bf16 a, bf16 b) {
    __nv_bfloat162 t = __halves2bfloat162(a, b);
    return *(U32*)&t;
}

#define CP16(s, g) \
    asm volatile("cp.async.cg.shared.global [%0], [%1], 16;" :: "r"(s), "l"(g))
#define CP_COMMIT() asm volatile("cp.async.commit_group;" ::: "memory")
#define CP_WAIT1()  asm volatile("cp.async.wait_group 1;" ::: "memory")

#define LDSM4(r, a) \
    asm volatile("ldmatrix.sync.aligned.m8n8.x4.shared.b16 {%0,%1,%2,%3}, [%4];" \
                 : "=r"((r)[0]), "=r"((r)[1]), "=r"((r)[2]), "=r"((r)[3]) : "r"(a))

__device__ __forceinline__ void mma16816(float* c, const U32* a, U32 b0, U32 b1) {
    asm volatile(
        "mma.sync.aligned.m16n8k16.row.col.f32.bf16.bf16.f32 "
        "{%0,%1,%2,%3}, {%4,%5,%6,%7}, {%8,%9}, {%0,%1,%2,%3};"
        : "+f"(c[0]), "+f"(c[1]), "+f"(c[2]), "+f"(c[3])
        : "r"(a[0]), "r"(a[1]), "r"(a[2]), "r"(a[3]), "r"(b0), "r"(b1));
}

// ---------------- SMEM layout ------------------------------------------------
// stage: Ah | Al | Bh | Bl, each 128 rows x 64 bf16 (128B rows, SW128-swizzled)
#define STAGE_B 65536
#define OFF_AH  0
#define OFF_AL  16384
#define OFF_BH  32768
#define OFF_BL  49152
#define NSTAGE  3
#define SMEMSZ  (NSTAGE * STAGE_B)

// ---------------- core: C(128x128 f32) = split-bf16 A · B^T -> smem Cs -------
// A rows m0..m0+127 K-major (stride lda); B rows n0..n0+127 K-major (stride ldb).
// Result left in smem as float Cs[128][130].
__device__ __forceinline__ void gemm_tile(
    char* smem,
    const bf16* __restrict__ Ah, const bf16* __restrict__ Al, size_t lda,
    const bf16* __restrict__ Bh, const bf16* __restrict__ Bl, size_t ldb,
    int m0, int n0, int K)
{
    const U32 sb = smem_u32(smem);
    const int t = threadIdx.x, lane = t & 31, wid = t >> 5;

    // ---- loader mapping: 256 threads, per tile: row=t>>1, 4x16B segs --------
    const int lrow = t >> 1, lhalf = t & 1;
    const bf16* pah = Ah + (size_t)(m0 + lrow) * lda + lhalf * 32;
    const bf16* pal = Al + (size_t)(m0 + lrow) * lda + lhalf * 32;
    const bf16* pbh = Bh + (size_t)(n0 + lrow) * ldb + lhalf * 32;
    const bf16* pbl = Bl + (size_t)(n0 + lrow) * ldb + lhalf * 32;
    U32 dsw[4];
#pragma unroll
    for (int i = 0; i < 4; i++)
        dsw[i] = lrow * 128 + 16 * ((((lhalf << 2) | i)) ^ (lrow & 7));

    const int nch = K >> 6;

    auto issue = [&](int c) {
        if (c < nch) {
            const U32 stb = sb + (c % NSTAGE) * STAGE_B;
            const bf16* a0 = pah + c * 64;
            const bf16* a1 = pal + c * 64;
            const bf16* b0 = pbh + c * 64;
            const bf16* b1 = pbl + c * 64;
#pragma unroll
            for (int i = 0; i < 4; i++) {
                CP16(stb + OFF_AH + dsw[i], a0 + i * 8);
                CP16(stb + OFF_AL + dsw[i], a1 + i * 8);
                CP16(stb + OFF_BH + dsw[i], b0 + i * 8);
                CP16(stb + OFF_BL + dsw[i], b1 + i * 8);
            }
        }
        CP_COMMIT();  // empty group past the end keeps wait_group accounting uniform
    };

    // ---- compute mapping: 8 warps as 2(m) x 4(n), warp tile 64x32 -----------
    const int wm = wid >> 2, wn = wid & 3;
    const int jj = lane >> 3;
    const int rl = ((jj & 1) << 3) + (lane & 7);  // row within 16-row block
    const int khalf = jj >> 1;                     // k-halves of 16
    const U32 aoff = (wm * 64 + rl) * 128;
    const U32 boff = (wn * 32 + rl) * 128;

    float acc[4][4][4];
#pragma unroll
    for (int i = 0; i < 4; i++)
#pragma unroll
        for (int j = 0; j < 4; j++)
#pragma unroll
            for (int r = 0; r < 4; r++) acc[i][j][r] = 0.0f;

    issue(0);
    issue(1);

    for (int c = 0; c < nch; c++) {
        CP_WAIT1();
        __syncthreads();
        issue(c + 2);

        const U32 stb = sb + (c % NSTAGE) * STAGE_B;
        const U32 pAh = stb + OFF_AH + aoff, pAl = stb + OFF_AL + aoff;
        const U32 pBh = stb + OFF_BH + boff, pBl = stb + OFF_BL + boff;

#pragma unroll
        for (int ks = 0; ks < 4; ks++) {
            const U32 sw = 16 * ((((ks << 1) | khalf)) ^ (lane & 7));
            U32 ah[4][4], bh[2][4];
#pragma unroll
            for (int i = 0; i < 4; i++) LDSM4(ah[i], pAh + i * 2048 + sw);
#pragma unroll
            for (int u = 0; u < 2; u++) LDSM4(bh[u], pBh + u * 2048 + sw);
#pragma unroll
            for (int i = 0; i < 4; i++)
#pragma unroll
                for (int j = 0; j < 4; j++)
                    mma16816(acc[i][j], ah[i], bh[j >> 1][j & 1], bh[j >> 1][2 + (j & 1)]);

            U32 bl[2][4];
#pragma unroll
            for (int u = 0; u < 2; u++) LDSM4(bl[u], pBl + u * 2048 + sw);
#pragma unroll
            for (int i = 0; i < 4; i++)
#pragma unroll
                for (int j = 0; j < 4; j++)
                    mma16816(acc[i][j], ah[i], bl[j >> 1][j & 1], bl[j >> 1][2 + (j & 1)]);

            U32 al[4][4];
#pragma unroll
            for (int i = 0; i < 4; i++) LDSM4(al[i], pAl + i * 2048 + sw);
#pragma unroll
            for (int i = 0; i < 4; i++)
#pragma unroll
                for (int j = 0; j < 4; j++)
                    mma16816(acc[i][j], al[i], bh[j >> 1][j & 1], bh[j >> 1][2 + (j & 1)]);
        }
    }

    __syncthreads();  // all compute done before smem is reused for Cs
    float* Cs = (float*)smem;
#pragma unroll
    for (int i = 0; i < 4; i++)
#pragma unroll
        for (int j = 0; j < 4; j++) {
            const int r = wm * 64 + i * 16 + (lane >> 2);
            const int col = wn * 32 + j * 8 + 2 * (lane & 3);
            *(float2*)&Cs[r * 130 + col]       = make_float2(acc[i][j][0], acc[i][j][1]);
            *(float2*)&Cs[(r + 8) * 130 + col] = make_float2(acc[i][j][2], acc[i][j][3]);
        }
    __syncthreads();
}

// ---------------- preprocessing ----------------------------------------------
__global__ __launch_bounds__(256) void split_x_kernel(const float* __restrict__ in) {
    size_t i = ((size_t)blockIdx.x * 256 + threadIdx.x) * 4;
    float4 v = *(const float4*)(in + i);
    bf16 h0 = __float2bfloat16(v.x), h1 = __float2bfloat16(v.y);
    bf16 h2 = __float2bfloat16(v.z), h3 = __float2bfloat16(v.w);
    bf16 l0 = __float2bfloat16(v.x - __bfloat162float(h0));
    bf16 l1 = __float2bfloat16(v.y - __bfloat162float(h1));
    bf16 l2 = __float2bfloat16(v.z - __bfloat162float(h2));
    bf16 l3 = __float2bfloat16(v.w - __bfloat162float(h3));
    *(uint2*)(g_xh + i) = make_uint2(pack2(h0, h1), pack2(h2, h3));
    *(uint2*)(g_xl + i) = make_uint2(pack2(l0, l1), pack2(l2, l3));
}

__global__ void wtrans_kernel(const float* __restrict__ Wq,
                              const float* __restrict__ Wk,
                              const float* __restrict__ Wv) {
    __shared__ float tl[32][33];
    const int z = blockIdx.z;
    const float* W = (z == 0) ? Wq : (z == 1) ? Wk : Wv;
    const int k0 = blockIdx.y * 32, n0 = blockIdx.x * 32;
    tl[threadIdx.y][threadIdx.x] = W[(size_t)(k0 + threadIdx.y) * F + n0 + threadIdx.x];
    __syncthreads();
    float v = tl[threadIdx.x][threadIdx.y];
    bf16 h = __float2bfloat16(v);
    bf16 l = __float2bfloat16(v - __bfloat162float(h));
    size_t o = (size_t)z * F * F + (size_t)(n0 + threadIdx.y) * F + k0 + threadIdx.x;
    g_wth[o] = h;
    g_wtl[o] = l;
}

// ---------------- GEMM kernels -----------------------------------------------
// QKV: z=0 -> q (split bf16), z=1 -> k (split), z=2 -> v (split + transpose)
__global__ __launch_bounds__(256, 1) void qkv_mma(
    const float* __restrict__ bq, const float* __restrict__ bk, const float* __restrict__ bv)
{
    extern __shared__ char smem[];
    const int z = blockIdx.z;
    const bf16* Bh = g_wth + (size_t)z * F * F;
    const bf16* Bl = g_wtl + (size_t)z * F * F;
    const float* bias = (z == 0) ? bq : (z == 1) ? bk : bv;
    const int m0 = blockIdx.y * 128, n0 = blockIdx.x * 128;

    gemm_tile(smem, g_xh, g_xl, F, Bh, Bl, F, m0, n0, F);
    const float* Cs = (const float*)smem;
    const int t = threadIdx.x;

    if (z < 2) {
        const int row = t >> 1, ch = (t & 1) * 64;
        bf16* oh = ((z == 0) ? g_qh : g_kh) + (size_t)(m0 + row) * F + n0 + ch;
        bf16* ol = ((z == 0) ? g_ql : g_kl) + (size_t)(m0 + row) * F + n0 + ch;
        const float* crow = Cs + row * 130 + ch;
        const float* brow = bias + n0 + ch;
#pragma unroll
        for (int c8 = 0; c8 < 64; c8 += 8) {
            U32 hp[4], lp[4];
#pragma unroll
            for (int j = 0; j < 4; j++) {
                float v0 = crow[c8 + 2 * j]     + brow[c8 + 2 * j];
                float v1 = crow[c8 + 2 * j + 1] + brow[c8 + 2 * j + 1];
                bf16 h0 = __float2bfloat16(v0), h1 = __float2bfloat16(v1);
                bf16 l0 = __float2bfloat16(v0 - __bfloat162float(h0));
                bf16 l1 = __float2bfloat16(v1 - __bfloat162float(h1));
                hp[j] = pack2(h0, h1);
                lp[j] = pack2(l0, l1);
            }
            *(uint4*)(oh + c8) = *(uint4*)hp;
            *(uint4*)(ol + c8) = *(uint4*)lp;
        }
    } else {
        // v: write transposed [b, n, s] so AV can consume K-major rows
        const int n = t >> 1, sh = (t & 1) * 64;
        const int b = m0 >> 12, s0 = (m0 & 4095) + sh;
        const float bias_n = bias[n0 + n];
        bf16* ovh = g_vth + ((size_t)b * F + n0 + n) * S + s0;
        bf16* ovl = g_vtl + ((size_t)b * F + n0 + n) * S + s0;
#pragma unroll
        for (int c8 = 0; c8 < 64; c8 += 8) {
            U32 hp[4], lp[4];
#pragma unroll
            for (int j = 0; j < 4; j++) {
                float v0 = Cs[(sh + c8 + 2 * j) * 130 + n]     + bias_n;
                float v1 = Cs[(sh + c8 + 2 * j + 1) * 130 + n] + bias_n;
                bf16 h0 = __float2bfloat16(v0), h1 = __float2bfloat16(v1);
                bf16 l0 = __float2bfloat16(v0 - __bfloat162float(h0));
                bf16 l1 = __float2bfloat16(v1 - __bfloat162float(h1));
                hp[j] = pack2(h0, h1);
                lp[j] = pack2(l0, l1);
            }
            *(uint4*)(ovh + c8) = *(uint4*)hp;
            *(uint4*)(ovl + c8) = *(uint4*)lp;
        }
    }
}

// scores[b] = (q[b] · k[b]^T) / 32 -> f32
__global__ __launch_bounds__(256, 1) void scores_mma() {
    extern __shared__ char smem[];
    const int b = blockIdx.z;
    const int m0 = blockIdx.y * 128, n0 = blockIdx.x * 128;
    const size_t qo = (size_t)b * S * F;

    gemm_tile(smem, g_qh + qo, g_ql + qo, F, g_kh + qo, g_kl + qo, F, m0, n0, F);
    const float* Cs = (const float*)smem;

    const int t = threadIdx.x;
    const int row = t >> 1, ch = (t & 1) * 64;
    float* orow = g_s + ((size_t)b * S + m0 + row) * S + n0 + ch;
    const float* crow = Cs + row * 130 + ch;
#pragma unroll
    for (int c4 = 0; c4 < 64; c4 += 4) {
        float4 f;
        f.x = crow[c4 + 0] * 0.03125f;
        f.y = crow[c4 + 1] * 0.03125f;
        f.z = crow[c4 + 2] * 0.03125f;
        f.w = crow[c4 + 3] * 0.03125f;
        *(float4*)(orow + c4) = f;
    }
}

// softmax rows of g_s -> split bf16 probabilities
__global__ __launch_bounds__(256) void softmax_kernel() {
    const size_t row = blockIdx.x;
    const float4* p4 = (const float4*)(g_s + row * S);
    const int t = threadIdx.x, lane = t & 31, wid = t >> 5;
    __shared__ float red[8];

    float4 v[4];
    float mx = -1e30f;
#pragma unroll
    for (int i = 0; i < 4; i++) {
        v[i] = p4[t + 256 * i];
        mx = fmaxf(mx, fmaxf(fmaxf(v[i].x, v[i].y), fmaxf(v[i].z, v[i].w)));
    }
#pragma unroll
    for (int o = 16; o; o >>= 1) mx = fmaxf(mx, __shfl_xor_sync(0xffffffffu, mx, o));
    if (lane == 0) red[wid] = mx;
    __syncthreads();
    if (t == 0) {
        float m = red[0];
#pragma unroll
        for (int i = 1; i < 8; i++) m = fmaxf(m, red[i]);
        red[0] = m;
    }
    __syncthreads();
    mx = red[0];
    __syncthreads();

    float sum = 0.0f;
#pragma unroll
    for (int i = 0; i < 4; i++) {
        v[i].x = __expf(v[i].x - mx);
        v[i].y = __expf(v[i].y - mx);
        v[i].z = __expf(v[i].z - mx);
        v[i].w = __expf(v[i].w - mx);
        sum += (v[i].x + v[i].y) + (v[i].z + v[i].w);
    }
#pragma unroll
    for (int o = 16; o; o >>= 1) sum += __shfl_xor_sync(0xffffffffu, sum, o);
    if (lane == 0) red[wid] = sum;
    __syncthreads();
    if (t == 0) {
        float s = 0.0f;
#pragma unroll
        for (int i = 0; i < 8; i++) s += red[i];
        red[0] = s;
    }
    __syncthreads();
    const float inv = 1.0f / red[0];

    bf16* ph = g_ph + row * S;
    bf16* pl = g_pl + row * S;
#pragma unroll
    for (int i = 0; i < 4; i++) {
        float p0 = v[i].x * inv, p1 = v[i].y * inv, p2 = v[i].z * inv, p3 = v[i].w * inv;
        bf16 h0 = __float2bfloat16(p0), h1 = __float2bfloat16(p1);
        bf16 h2 = __float2bfloat16(p2), h3 = __float2bfloat16(p3);
        bf16 l0 = __float2bfloat16(p0 - __bfloat162float(h0));
        bf16 l1 = __float2bfloat16(p1 - __bfloat162float(h1));
        bf16 l2 = __float2bfloat16(p2 - __bfloat162float(h2));
        bf16 l3 = __float2bfloat16(p3 - __bfloat162float(h3));
        const int col = (t + 256 * i) * 4;
        *(uint2*)(ph + col) = make_uint2(pack2(h0, h1), pack2(h2, h3));
        *(uint2*)(pl + col) = make_uint2(pack2(l0, l1), pack2(l2, l3));
    }
}

// out[b] = P[b] · V[b]  (A = P split, B = V^T split, K = 4096)
__global__ __launch_bounds__(256, 1) void av_mma(float* __restrict__ out) {
    extern __shared__ char smem[];
    const int b = blockIdx.z;
    const int m0 = blockIdx.y * 128, n0 = blockIdx.x * 128;
    const size_t po = (size_t)b * S * S;
    const size_t vo = (size_t)b * F * S;

    gemm_tile(smem, g_ph + po, g_pl + po, S, g_vth + vo, g_vtl + vo, S, m0, n0, S);
    const float* Cs = (const float*)smem;

    const int t = threadIdx.x;
    const int row = t >> 1, ch = (t & 1) * 64;
    float* orow = out + ((size_t)b * S + m0 + row) * F + n0 + ch;
    const float* crow = Cs + row * 130 + ch;
#pragma unroll
    for (int c4 = 0; c4 < 64; c4 += 4) {
        float4 f;
        f.x = crow[c4 + 0];
        f.y = crow[c4 + 1];
        f.z = crow[c4 + 2];
        f.w = crow[c4 + 3];
        *(float4*)(orow + c4) = f;
    }
}

// ---------------- entry ------------------------------------------------------
extern "C" void kernel_launch(void* const* d_in, const int* in_sizes, int n_in,
                              void* d_out, int out_size)
{
    (void)in_sizes; (void)n_in; (void)out_size;
    const float* x  = (const float*)d_in[0];
    const float* Wq = (const float*)d_in[1];
    const float* bq = (const float*)d_in[2];
    const float* Wk = (const float*)d_in[3];
    const float* bk = (const float*)d_in[4];
    const float* Wv = (const float*)d_in[5];
    const float* bv = (const float*)d_in[6];
    float* out = (float*)d_out;

    cudaFuncSetAttribute(qkv_mma,    cudaFuncAttributeMaxDynamicSharedMemorySize, SMEMSZ);
    cudaFuncSetAttribute(scores_mma, cudaFuncAttributeMaxDynamicSharedMemorySize, SMEMSZ);
    cudaFuncSetAttribute(av_mma,     cudaFuncAttributeMaxDynamicSharedMemorySize, SMEMSZ);

    split_x_kernel<<<16384, 256>>>(x);
    wtrans_kernel<<<dim3(32, 32, 3), dim3(32, 32)>>>(Wq, Wk, Wv);
    qkv_mma<<<dim3(8, 128, 3), 256, SMEMSZ>>>(bq, bk, bv);
    scores_mma<<<dim3(32, 32, 4), 256, SMEMSZ>>>();
    softmax_kernel<<<16384, 256>>>();
    av_mma<<<dim3(8, 32, 4), 256, SMEMSZ>>>(out);
}